// round 1
// baseline (speedup 1.0000x reference)
#include <cuda_runtime.h>
#include <cstdint>

#define NN 500
#define GG 128
#define HH 200
#define WW 304
#define HWPX (HH * WW)          // 60800
#define WORDS 1900              // HWPX / 32, exact
#define WSTRIDE 1920            // padded row stride (u32 words), 16B-multiple
#define MAXPAIRS (NN * (NN - 1) / 2)   // 124750
#define MASK_THR 0.005f
#define SIGMA 2.0f

// ---- device scratch (no allocations allowed) ----
__device__ __align__(16) unsigned int g_bits[NN * WSTRIDE]; // packed hard masks
__device__ int   g_area[NN];      // sum_masks (popcount)
__device__ float g_scores[NN];    // cate_scores * seg_score
__device__ float g_comp[NN];      // comp_iou (column max)
__device__ float g_coef[NN];      // running min of decay terms
__device__ int   g_npairs;
__device__ unsigned int g_pair_ij[MAXPAIRS];
__device__ float g_pair_d[MAXPAIRS];

// ============================================================
// Kernel A: decode masks, pack bits, compute rescored scores
// ============================================================
__global__ __launch_bounds__(256) void decode_kernel(
    const float* __restrict__ cate_scores,
    const float* __restrict__ segx,
    const float* __restrict__ segy,
    const int* __restrict__ x_inds,
    const int* __restrict__ y_inds)
{
    const int n = blockIdx.x;
    const int tid = threadIdx.x;

    const int xi = x_inds[n];
    const int yi = y_inds[n];
    const float4* __restrict__ rx = reinterpret_cast<const float4*>(segx + (size_t)xi * HWPX);
    const float4* __restrict__ ry = reinterpret_cast<const float4*>(segy + (size_t)yi * HWPX);

    int   area = 0;
    float ssum = 0.0f;

    // word w covers pixels [32w, 32w+32) = float4 indices [8w, 8w+8)
    for (int w = tid; w < WORDS; w += 256) {
        unsigned int bits = 0;
        const int f4 = w * 8;
#pragma unroll
        for (int q = 0; q < 8; q++) {
            float4 a = rx[f4 + q];
            float4 b = ry[f4 + q];
            float s0 = a.x * b.x;
            float s1 = a.y * b.y;
            float s2 = a.z * b.z;
            float s3 = a.w * b.w;
            if (s0 > MASK_THR) { bits |= 1u << (q * 4 + 0); ssum += s0; }
            if (s1 > MASK_THR) { bits |= 1u << (q * 4 + 1); ssum += s1; }
            if (s2 > MASK_THR) { bits |= 1u << (q * 4 + 2); ssum += s2; }
            if (s3 > MASK_THR) { bits |= 1u << (q * 4 + 3); ssum += s3; }
        }
        g_bits[n * WSTRIDE + w] = bits;
        area += __popc(bits);
    }
    // zero the pad words once (so uint4 reads in kernel B see zeros)
    if (tid < WSTRIDE - WORDS)
        g_bits[n * WSTRIDE + WORDS + tid] = 0u;

    // block reduction (8 warps)
    __shared__ float s_sum[8];
    __shared__ int   s_area[8];
#pragma unroll
    for (int off = 16; off > 0; off >>= 1) {
        ssum += __shfl_down_sync(0xffffffffu, ssum, off);
        area += __shfl_down_sync(0xffffffffu, area, off);
    }
    if ((tid & 31) == 0) { s_sum[tid >> 5] = ssum; s_area[tid >> 5] = area; }
    __syncthreads();
    if (tid == 0) {
        float tsum = 0.0f; int tarea = 0;
#pragma unroll
        for (int k = 0; k < 8; k++) { tsum += s_sum[k]; tarea += s_area[k]; }
        g_area[n] = tarea;
        float seg_score = tsum / fmaxf((float)tarea, 1.0f);
        g_scores[n] = cate_scores[n] * seg_score;
        g_comp[n] = 0.0f;
        g_coef[n] = 1.0f;
        if (n == 0) g_npairs = 0;
    }
}

// ============================================================
// Kernel B: same-label pair intersections (one warp per pair)
// grid = (63, NN): blockIdx.y = i, warp covers j = i+1 + wj
// ============================================================
__global__ __launch_bounds__(256) void pair_kernel(const int* __restrict__ labels)
{
    const int i = blockIdx.y;
    const int warp = threadIdx.x >> 5;
    const int lane = threadIdx.x & 31;
    const int j = i + 1 + (blockIdx.x * 8 + warp);
    if (j >= NN) return;
    if (labels[i] != labels[j]) return;

    const uint4* __restrict__ bi = reinterpret_cast<const uint4*>(g_bits + i * WSTRIDE);
    const uint4* __restrict__ bj = reinterpret_cast<const uint4*>(g_bits + j * WSTRIDE);

    int inter = 0;
    // WSTRIDE/4 = 480 uint4 per row (pad words are zero)
    for (int w = lane; w < WSTRIDE / 4; w += 32) {
        uint4 a = bi[w];
        uint4 b = bj[w];
        inter += __popc(a.x & b.x) + __popc(a.y & b.y)
               + __popc(a.z & b.z) + __popc(a.w & b.w);
    }
#pragma unroll
    for (int off = 16; off > 0; off >>= 1)
        inter += __shfl_down_sync(0xffffffffu, inter, off);

    if (lane == 0) {
        float uni = (float)(g_area[i] + g_area[j] - inter);
        float iou = (float)inter / fmaxf(uni, 1e-6f);
        // non-negative float: int ordering is monotonic
        atomicMax(reinterpret_cast<int*>(&g_comp[j]), __float_as_int(iou));
        int pos = atomicAdd(&g_npairs, 1);
        g_pair_ij[pos] = ((unsigned)i << 16) | (unsigned)j;
        g_pair_d[pos] = iou;
    }
}

// ============================================================
// Kernel C: decay terms -> atomicMin into coef[j]
// ============================================================
__global__ __launch_bounds__(256) void decay_kernel()
{
    const int p = blockIdx.x * blockDim.x + threadIdx.x;
    if (p >= g_npairs) return;
    unsigned ij = g_pair_ij[p];
    int i = (int)(ij >> 16);
    int j = (int)(ij & 0xffffu);
    float d = g_pair_d[p];
    float c = g_comp[i];
    // exp(-sigma*d^2) / exp(-sigma*c^2) = exp(sigma*(c^2 - d^2)); always > 0
    float term = __expf(SIGMA * (c * c - d * d));
    atomicMin(reinterpret_cast<int*>(&g_coef[j]), __float_as_int(term));
}

// ============================================================
// Kernel D: final scores
// ============================================================
__global__ void final_kernel(float* __restrict__ out)
{
    const int n = blockIdx.x * blockDim.x + threadIdx.x;
    if (n < NN) {
        float coef = fminf(g_coef[n], 1.0f);  // row 0 of the full matrix contributes exactly 1
        out[n] = g_scores[n] * coef;
    }
}

extern "C" void kernel_launch(void* const* d_in, const int* in_sizes, int n_in,
                              void* d_out, int out_size)
{
    const float* cate_scores = (const float*)d_in[0];
    const float* segx        = (const float*)d_in[1];
    const float* segy        = (const float*)d_in[2];
    const int*   labels      = (const int*)d_in[3];
    const int*   x_inds      = (const int*)d_in[4];
    const int*   y_inds      = (const int*)d_in[5];
    float* out = (float*)d_out;

    decode_kernel<<<NN, 256>>>(cate_scores, segx, segy, x_inds, y_inds);
    pair_kernel<<<dim3(63, NN), 256>>>(labels);
    decay_kernel<<<(MAXPAIRS + 255) / 256, 256>>>();
    final_kernel<<<2, 256>>>(out);
}